// round 1
// baseline (speedup 1.0000x reference)
#include <cuda_runtime.h>
#include <cstdint>

#define NS      65536
#define HALF    32
#define NHID    512
#define NOUT    736      // (3*8-1)*32
#define KB      8
#define TB      3.0f

// ---------------- static scratch (allocation-free rule) ----------------
__device__ float g_bufA[(size_t)NS * NHID];
__device__ float g_bufB[(size_t)NS * NHID];
__device__ float g_bufC[(size_t)NS * NOUT];

// ---------------- SGEMM: C[M,N] = act(A[M,K] @ W[K,N] + b) ----------------
// BM=128, BN=128, BK=8, 256 threads, 8x8 per thread. M = NS (multiple of 128).
template <int ACT>
__global__ void __launch_bounds__(256) sgemm_kernel(
    const float* __restrict__ A, int lda,
    const float* __restrict__ W,      // [K,N] row-major
    const float* __restrict__ bias,   // [N]
    float* __restrict__ C,            // [M,N] row-major (ldc = N)
    int N, int K)
{
    __shared__ float As[8][128];
    __shared__ float Bs[8][128];

    const int tid   = threadIdx.x;
    const int row_c = blockIdx.y * 128;
    const int col_c = blockIdx.x * 128;

    const int tx = tid & 15;        // 0..15 -> cols
    const int ty = tid >> 4;        // 0..15 -> rows

    // A-tile load: one float4 per thread. row = tid>>1 (0..127), k-offset = (tid&1)*4
    const int aRow = tid >> 1;
    const int aCol = (tid & 1) * 4;
    // B-tile load: one float4 per thread. k = tid>>5 (0..7), col = (tid&31)*4
    const int bRow = tid >> 5;
    const int bCol = (tid & 31) * 4;

    const float* Abase = A + (size_t)(row_c + aRow) * lda + aCol;

    float acc[8][8];
#pragma unroll
    for (int i = 0; i < 8; i++)
#pragma unroll
        for (int j = 0; j < 8; j++) acc[i][j] = 0.f;

    for (int k0 = 0; k0 < K; k0 += 8) {
        // load A tile (transposed into As[k][m])
        float4 av = *reinterpret_cast<const float4*>(Abase + k0);
        As[aCol + 0][aRow] = av.x;
        As[aCol + 1][aRow] = av.y;
        As[aCol + 2][aRow] = av.z;
        As[aCol + 3][aRow] = av.w;
        // load B tile
        const int gcol = col_c + bCol;
        float4 bv = make_float4(0.f, 0.f, 0.f, 0.f);
        if (gcol < N)  // N is a multiple of 4; float4 fully in or out
            bv = *reinterpret_cast<const float4*>(W + (size_t)(k0 + bRow) * N + gcol);
        Bs[bRow][bCol + 0] = bv.x;
        Bs[bRow][bCol + 1] = bv.y;
        Bs[bRow][bCol + 2] = bv.z;
        Bs[bRow][bCol + 3] = bv.w;
        __syncthreads();

#pragma unroll
        for (int kk = 0; kk < 8; kk++) {
            float4 a0 = *reinterpret_cast<const float4*>(&As[kk][ty * 8]);
            float4 a1 = *reinterpret_cast<const float4*>(&As[kk][ty * 8 + 4]);
            float4 b0 = *reinterpret_cast<const float4*>(&Bs[kk][tx * 8]);
            float4 b1 = *reinterpret_cast<const float4*>(&Bs[kk][tx * 8 + 4]);
            float a[8] = {a0.x, a0.y, a0.z, a0.w, a1.x, a1.y, a1.z, a1.w};
            float b[8] = {b0.x, b0.y, b0.z, b0.w, b1.x, b1.y, b1.z, b1.w};
#pragma unroll
            for (int i = 0; i < 8; i++)
#pragma unroll
                for (int j = 0; j < 8; j++)
                    acc[i][j] = fmaf(a[i], b[j], acc[i][j]);
        }
        __syncthreads();
    }

    // epilogue: bias + optional leaky-relu, bounds-checked on N
#pragma unroll
    for (int i = 0; i < 8; i++) {
        const size_t crow = (size_t)(row_c + ty * 8 + i);
        float* cp = C + crow * N;
#pragma unroll
        for (int j = 0; j < 8; j++) {
            const int col = col_c + tx * 8 + j;
            if (col < N) {
                float v = acc[i][j] + bias[col];
                if (ACT) v = (v > 0.f) ? v : 0.2f * v;
                cp[col] = v;
            }
        }
    }
}

// ---------------- spline kernel ----------------
// One thread per (sample, dim). One warp == one sample (32 dims) -> shuffle logdet.
__device__ __forceinline__ float softplusf(float x) {
    return (x > 0.f) ? (x + log1pf(expf(-x))) : log1pf(expf(x));
}

__global__ void __launch_bounds__(256) spline_kernel(
    const float* __restrict__ y, int ldy,
    const float* __restrict__ cond,    // [NS, NOUT]
    float* __restrict__ out_y, int ldo,
    float* __restrict__ logdet, int add)
{
    const int gid = blockIdx.x * 256 + threadIdx.x;
    const int s   = gid >> 5;
    const int dim = gid & 31;
    if (s >= NS) return;

    const float* p = cond + (size_t)s * NOUT + dim * 23;
    const float x = y[(size_t)s * ldy + dim];

    float rw[KB], rh[KB];
#pragma unroll
    for (int i = 0; i < KB; i++) rw[i] = p[i];
#pragma unroll
    for (int i = 0; i < KB; i++) rh[i] = p[KB + i];

    // ---- W = 2*TB*softmax(raw_w); widths = MIN_BW + (1-8*MIN_BW)*softmax(W) ----
    float cw[KB + 1], wid[KB];
    {
        float m = rw[0];
#pragma unroll
        for (int i = 1; i < KB; i++) m = fmaxf(m, rw[i]);
        float s1 = 0.f, e[KB];
#pragma unroll
        for (int i = 0; i < KB; i++) { e[i] = expf(rw[i] - m); s1 += e[i]; }
        float inv1 = 1.f / s1, Wv[KB];
#pragma unroll
        for (int i = 0; i < KB; i++) Wv[i] = 2.f * TB * e[i] * inv1;
        float m2 = Wv[0];
#pragma unroll
        for (int i = 1; i < KB; i++) m2 = fmaxf(m2, Wv[i]);
        float s2 = 0.f;
#pragma unroll
        for (int i = 0; i < KB; i++) { e[i] = expf(Wv[i] - m2); s2 += e[i]; }
        float inv2 = 1.f / s2;
        float run = 0.f;
        cw[0] = -TB;
#pragma unroll
        for (int i = 0; i < KB; i++) {
            float w = 0.001f + (1.f - 0.001f * KB) * e[i] * inv2;
            run += w;
            cw[i + 1] = 2.f * TB * run - TB;
        }
        cw[KB] = TB;
#pragma unroll
        for (int i = 0; i < KB; i++) wid[i] = cw[i + 1] - cw[i];
    }

    // ---- heights, same recipe ----
    float ch[KB + 1], hei[KB];
    {
        float m = rh[0];
#pragma unroll
        for (int i = 1; i < KB; i++) m = fmaxf(m, rh[i]);
        float s1 = 0.f, e[KB];
#pragma unroll
        for (int i = 0; i < KB; i++) { e[i] = expf(rh[i] - m); s1 += e[i]; }
        float inv1 = 1.f / s1, Hv[KB];
#pragma unroll
        for (int i = 0; i < KB; i++) Hv[i] = 2.f * TB * e[i] * inv1;
        float m2 = Hv[0];
#pragma unroll
        for (int i = 1; i < KB; i++) m2 = fmaxf(m2, Hv[i]);
        float s2 = 0.f;
#pragma unroll
        for (int i = 0; i < KB; i++) { e[i] = expf(Hv[i] - m2); s2 += e[i]; }
        float inv2 = 1.f / s2;
        float run = 0.f;
        ch[0] = -TB;
#pragma unroll
        for (int i = 0; i < KB; i++) {
            float h = 0.001f + (1.f - 0.001f * KB) * e[i] * inv2;
            run += h;
            ch[i + 1] = 2.f * TB * run - TB;
        }
        ch[KB] = TB;
#pragma unroll
        for (int i = 0; i < KB; i++) hei[i] = ch[i + 1] - ch[i];
    }

    // ---- derivs = MIN_D + softplus(pad(softplus(raw_d), const)) ----
    float der[KB + 1];
    {
        const float CONST = 0.5397432446f; // log(exp(1-MIN_D)-1)
        der[0] = 0.001f + softplusf(CONST);
        der[KB] = der[0];
#pragma unroll
        for (int i = 0; i < KB - 1; i++)
            der[i + 1] = 0.001f + softplusf(softplusf(p[2 * KB + i]));
    }

    // ---- bin search (matches reference: count xc >= cw_e) ----
    const bool inside = (x >= -TB) && (x <= TB);
    const float xc = fminf(fmaxf(x, -TB), TB);
    int cnt = 0;
#pragma unroll
    for (int j = 0; j <= KB; j++) {
        float ce = cw[j] + ((j == KB) ? 1e-6f : 0.f);
        cnt += (xc >= ce) ? 1 : 0;
    }
    int idx = min(max(cnt - 1, 0), KB - 1);

    float in_cw = 0.f, in_w = 1.f, in_ch = 0.f, in_h = 1.f, in_der = 1.f, in_der1 = 1.f;
#pragma unroll
    for (int j = 0; j < KB; j++) {
        if (j == idx) {
            in_cw = cw[j]; in_w = wid[j]; in_ch = ch[j]; in_h = hei[j];
            in_der = der[j]; in_der1 = der[j + 1];
        }
    }
    const float in_d = in_h / in_w;

    const float theta = (xc - in_cw) / in_w;
    const float t1mt  = theta * (1.f - theta);
    const float num   = in_h * (in_d * theta * theta + in_der * t1mt);
    const float den   = in_d + (in_der + in_der1 - 2.f * in_d) * t1mt;
    const float outv  = in_ch + num / den;
    const float omt   = 1.f - theta;
    const float dnum  = in_d * in_d * (in_der1 * theta * theta + 2.f * in_d * t1mt + in_der * omt * omt);
    float lad = logf(dnum) - 2.f * logf(den);

    out_y[(size_t)s * ldo + dim] = inside ? outv : x;
    lad = inside ? lad : 0.f;

    // warp reduction: one warp covers exactly this sample's 32 dims
#pragma unroll
    for (int off = 16; off > 0; off >>= 1)
        lad += __shfl_down_sync(0xffffffffu, lad, off);
    if (dim == 0) {
        if (add) logdet[s] += lad;
        else     logdet[s]  = lad;
    }
}

// ---------------- launch ----------------
extern "C" void kernel_launch(void* const* d_in, const int* in_sizes, int n_in,
                              void* d_out, int out_size)
{
    const float* x    = (const float*)d_in[0];
    const float* f1w1 = (const float*)d_in[1];
    const float* f1b1 = (const float*)d_in[2];
    const float* f1w2 = (const float*)d_in[3];
    const float* f1b2 = (const float*)d_in[4];
    const float* f1w3 = (const float*)d_in[5];
    const float* f1b3 = (const float*)d_in[6];
    const float* f1w4 = (const float*)d_in[7];
    const float* f1b4 = (const float*)d_in[8];
    const float* f2w1 = (const float*)d_in[9];
    const float* f2b1 = (const float*)d_in[10];
    const float* f2w2 = (const float*)d_in[11];
    const float* f2b2 = (const float*)d_in[12];
    const float* f2w3 = (const float*)d_in[13];
    const float* f2b3 = (const float*)d_in[14];
    const float* f2w4 = (const float*)d_in[15];
    const float* f2b4 = (const float*)d_in[16];

    float* out    = (float*)d_out;                 // [NS,64] then [NS] logdet
    float* logdet = out + (size_t)NS * 64;

    float *bufA, *bufB, *bufC;
    cudaGetSymbolAddress((void**)&bufA, g_bufA);
    cudaGetSymbolAddress((void**)&bufB, g_bufB);
    cudaGetSymbolAddress((void**)&bufC, g_bufC);

    const dim3 blk(256);
    const dim3 g512(NHID / 128, NS / 128);         // (4, 512)
    const dim3 g736((NOUT + 127) / 128, NS / 128); // (6, 512)
    const int splineBlocks = (NS * 32) / 256;

    // ---- coupling 1: MLP(lower) transforms upper ----
    sgemm_kernel<1><<<g512, blk>>>(x,      64,  f1w1, f1b1, bufA, NHID, HALF);
    sgemm_kernel<1><<<g512, blk>>>(bufA, NHID,  f1w2, f1b2, bufB, NHID, NHID);
    sgemm_kernel<1><<<g512, blk>>>(bufB, NHID,  f1w3, f1b3, bufA, NHID, NHID);
    sgemm_kernel<0><<<g736, blk>>>(bufA, NHID,  f1w4, f1b4, bufC, NOUT, NHID);
    spline_kernel<<<splineBlocks, blk>>>(x + HALF, 64, bufC, out + HALF, 64, logdet, 0);

    // ---- coupling 2: MLP(new upper) transforms lower ----
    sgemm_kernel<1><<<g512, blk>>>(out + HALF, 64, f2w1, f2b1, bufA, NHID, HALF);
    sgemm_kernel<1><<<g512, blk>>>(bufA, NHID,  f2w2, f2b2, bufB, NHID, NHID);
    sgemm_kernel<1><<<g512, blk>>>(bufB, NHID,  f2w3, f2b3, bufA, NHID, NHID);
    sgemm_kernel<0><<<g736, blk>>>(bufA, NHID,  f2w4, f2b4, bufC, NOUT, NHID);
    spline_kernel<<<splineBlocks, blk>>>(x, 64, bufC, out, 64, logdet, 1);
}

// round 3
// speedup vs baseline: 3.1180x; 3.1180x over previous
#include <cuda_runtime.h>
#include <cuda_bf16.h>
#include <cstdint>

#define NS      65536
#define HALF    32
#define NHID    512
#define NOUT    736
#define NOUTP   768
#define KB      8
#define TB      3.0f

#define BM      128
#define BN      128
#define BKE     64
#define NTHR    256

// smem: 4 planes of 128x64 bf16 (16KB each) per stage, 2 stages
#define SA_H    0
#define SA_L    16384
#define SB_H    32768
#define SB_L    49152
#define STAGE   65536
#define SMEM_TOTAL (2*STAGE)

// ================= static scratch =================
__device__ __nv_bfloat16 g_xH[(size_t)NS*64];
__device__ __nv_bfloat16 g_xL[(size_t)NS*64];
__device__ __nv_bfloat16 g_aH0[(size_t)NS*NHID];
__device__ __nv_bfloat16 g_aL0[(size_t)NS*NHID];
__device__ __nv_bfloat16 g_aH1[(size_t)NS*NHID];
__device__ __nv_bfloat16 g_aL1[(size_t)NS*NHID];
__device__ float         g_bufC[(size_t)NS*NOUTP];
__device__ __nv_bfloat16 g_w1H[2][512*64],  g_w1L[2][512*64];
__device__ __nv_bfloat16 g_w2H[2][512*512], g_w2L[2][512*512];
__device__ __nv_bfloat16 g_w3H[2][512*512], g_w3L[2][512*512];
__device__ __nv_bfloat16 g_w4H[2][768*512], g_w4L[2][768*512];
__device__ float         g_b4p[2][NOUTP];

// ================= helpers =================
__device__ __forceinline__ uint32_t smem_u32(const void* p) {
    uint32_t a;
    asm("{ .reg .u64 t; cvta.to.shared.u64 t, %1; cvt.u32.u64 %0, t; }" : "=r"(a) : "l"(p));
    return a;
}
#define SWZ(x) ((x) ^ (((x) >> 3) & 0x70))

#define CP16(dst, src) asm volatile("cp.async.cg.shared.global [%0], [%1], 16;" :: "r"(dst), "l"(src))
#define CP_COMMIT()    asm volatile("cp.async.commit_group;" ::: "memory")
#define CP_WAIT(N)     asm volatile("cp.async.wait_group %0;" :: "n"(N) : "memory")

#define LDSM4(r, a) \
    asm volatile("ldmatrix.sync.aligned.m8n8.x4.shared.b16 {%0,%1,%2,%3}, [%4];" \
        : "=r"((r)[0]), "=r"((r)[1]), "=r"((r)[2]), "=r"((r)[3]) : "r"(a))

#define MMA16816(c, a, b0, b1) \
    asm volatile("mma.sync.aligned.m16n8k16.row.col.f32.bf16.bf16.f32 " \
        "{%0,%1,%2,%3}, {%4,%5,%6,%7}, {%8,%9}, {%0,%1,%2,%3};" \
        : "+f"((c)[0]), "+f"((c)[1]), "+f"((c)[2]), "+f"((c)[3]) \
        : "r"((a)[0]), "r"((a)[1]), "r"((a)[2]), "r"((a)[3]), "r"(b0), "r"(b1))

// ================= GEMM =================
// C[M,N'] = act(A[M,K'] @ B[N',K']^T + bias); split bf16x2 operands, 3-term HMMA.
template <int KT, int ACT, int SPLIT>
__global__ void __launch_bounds__(NTHR, 1) gemm_bf16x2(
    const __nv_bfloat16* __restrict__ Ah, const __nv_bfloat16* __restrict__ Al, int lda,
    const __nv_bfloat16* __restrict__ Bh, const __nv_bfloat16* __restrict__ Bl,
    const float* __restrict__ bias,
    __nv_bfloat16* __restrict__ Ch, __nv_bfloat16* __restrict__ Cl,
    float* __restrict__ Cf, int ldc)
{
    extern __shared__ __align__(1024) char smem[];
    const uint32_t sb = smem_u32(smem);
    const int tid  = threadIdx.x;
    const int wid  = tid >> 5;
    const int l    = tid & 31;
    const int wm   = wid & 3;          // 4 warps over M -> 32 rows each
    const int wn   = wid >> 2;         // 2 warps over N -> 64 cols each
    const int row0 = blockIdx.y * BM;
    const int col0 = blockIdx.x * BN;
    const int ldb  = KT * BKE;

    float acc[2][8][4];
#pragma unroll
    for (int i = 0; i < 2; i++)
#pragma unroll
        for (int j = 0; j < 8; j++)
#pragma unroll
            for (int q = 0; q < 4; q++) acc[i][j][q] = 0.f;

    auto load_tile = [&](int s, int m) {
        const uint32_t sbase = sb + s * STAGE;
        const int koff = m * BKE;
#pragma unroll
        for (int i = 0; i < 4; i++) {
            int c = tid + i * NTHR;          // 0..1023: 128 rows x 8 chunks
            int r = c >> 3, q = c & 7;
            uint32_t off = SWZ(r * 128 + q * 16);
            CP16(sbase + SA_H + off, Ah + (size_t)(row0 + r) * lda + koff + q * 8);
            CP16(sbase + SA_L + off, Al + (size_t)(row0 + r) * lda + koff + q * 8);
            CP16(sbase + SB_H + off, Bh + (size_t)(col0 + r) * ldb + koff + q * 8);
            CP16(sbase + SB_L + off, Bl + (size_t)(col0 + r) * ldb + koff + q * 8);
        }
    };

    auto compute = [&](int s) {
        const uint32_t AhB = sb + s * STAGE + SA_H;
        const uint32_t AlB = sb + s * STAGE + SA_L;
        const uint32_t BhB = sb + s * STAGE + SB_H;
        const uint32_t BlB = sb + s * STAGE + SB_L;
#pragma unroll
        for (int ks = 0; ks < 4; ks++) {
            uint32_t ah[2][4], al[2][4];
#pragma unroll
            for (int i = 0; i < 2; i++) {
                int row = wm * 32 + i * 16 + (l & 15);
                int colb = (ks * 16 + (l >> 4) * 8) * 2;
                uint32_t off = row * 128 + (colb ^ ((row & 7) << 4));
                LDSM4(ah[i], AhB + off);
                LDSM4(al[i], AlB + off);
            }
            uint32_t bh[4][4], bl[4][4];
#pragma unroll
            for (int j16 = 0; j16 < 4; j16++) {
                int n = wn * 64 + j16 * 16 + (l & 7) + ((l >> 4) << 3);
                int colb = (ks * 16 + ((l >> 3) & 1) * 8) * 2;
                uint32_t off = n * 128 + (colb ^ ((n & 7) << 4));
                LDSM4(bh[j16], BhB + off);
                LDSM4(bl[j16], BlB + off);
            }
#pragma unroll
            for (int i = 0; i < 2; i++)
#pragma unroll
                for (int j16 = 0; j16 < 4; j16++)
#pragma unroll
                    for (int hf = 0; hf < 2; hf++) {
                        const int j = j16 * 2 + hf;
                        MMA16816(acc[i][j], ah[i], bh[j16][hf*2], bh[j16][hf*2+1]);
                        MMA16816(acc[i][j], ah[i], bl[j16][hf*2], bl[j16][hf*2+1]);
                        MMA16816(acc[i][j], al[i], bh[j16][hf*2], bh[j16][hf*2+1]);
                    }
        }
    };

    load_tile(0, 0); CP_COMMIT();
#pragma unroll
    for (int kt = 0; kt < KT; kt++) {
        if (kt + 1 < KT) { load_tile((kt + 1) & 1, kt + 1); CP_COMMIT(); }
        if (kt + 1 < KT) CP_WAIT(1); else CP_WAIT(0);
        __syncthreads();
        compute(kt & 1);
        __syncthreads();
    }

    // ---- epilogue ----
#pragma unroll
    for (int i = 0; i < 2; i++) {
        const int r0 = row0 + wm * 32 + i * 16 + (l >> 2);
#pragma unroll
        for (int j = 0; j < 8; j++) {
            const int c = col0 + wn * 64 + j * 8 + (l & 3) * 2;
            const float b0 = bias[c], b1 = bias[c + 1];
            float v0 = acc[i][j][0] + b0, v1 = acc[i][j][1] + b1;
            float v2 = acc[i][j][2] + b0, v3 = acc[i][j][3] + b1;
            if (ACT) {
                v0 = (v0 > 0.f) ? v0 : 0.2f * v0;
                v1 = (v1 > 0.f) ? v1 : 0.2f * v1;
                v2 = (v2 > 0.f) ? v2 : 0.2f * v2;
                v3 = (v3 > 0.f) ? v3 : 0.2f * v3;
            }
            if (SPLIT) {
                __nv_bfloat162 h01, h23, l01, l23;
                __nv_bfloat16 h;
                h = __float2bfloat16(v0); h01.x = h; l01.x = __float2bfloat16(v0 - __bfloat162float(h));
                h = __float2bfloat16(v1); h01.y = h; l01.y = __float2bfloat16(v1 - __bfloat162float(h));
                h = __float2bfloat16(v2); h23.x = h; l23.x = __float2bfloat16(v2 - __bfloat162float(h));
                h = __float2bfloat16(v3); h23.y = h; l23.y = __float2bfloat16(v3 - __bfloat162float(h));
                *(__nv_bfloat162*)(Ch + (size_t)r0 * ldc + c)       = h01;
                *(__nv_bfloat162*)(Cl + (size_t)r0 * ldc + c)       = l01;
                *(__nv_bfloat162*)(Ch + (size_t)(r0 + 8) * ldc + c) = h23;
                *(__nv_bfloat162*)(Cl + (size_t)(r0 + 8) * ldc + c) = l23;
            } else {
                *(float2*)(Cf + (size_t)r0 * ldc + c)       = make_float2(v0, v1);
                *(float2*)(Cf + (size_t)(r0 + 8) * ldc + c) = make_float2(v2, v3);
            }
        }
    }
}

// ================= weight prep: transpose + pad + bf16 split =================
__global__ void prep_w(const float* __restrict__ W, const float* __restrict__ b,
                       int K, int N, int Kpad, int Npad,
                       __nv_bfloat16* __restrict__ WtH, __nv_bfloat16* __restrict__ WtL,
                       float* __restrict__ bpad)
{
    int idx = blockIdx.x * 256 + threadIdx.x;
    if (idx >= Npad * Kpad) return;
    int n = idx / Kpad, k = idx - n * Kpad;
    float v = (k < K && n < N) ? W[(size_t)k * N + n] : 0.f;
    __nv_bfloat16 h = __float2bfloat16(v);
    WtH[idx] = h;
    WtL[idx] = __float2bfloat16(v - __bfloat162float(h));
    if (bpad && k == 0) bpad[n] = (n < N) ? b[n] : 0.f;
}

__global__ void split_x(const float* __restrict__ x,
                        __nv_bfloat16* __restrict__ H, __nv_bfloat16* __restrict__ L)
{
    int idx = blockIdx.x * 256 + threadIdx.x;
    int s = idx >> 6, d = idx & 63;
    float v = (d < HALF) ? x[(size_t)s * 64 + d] : 0.f;
    __nv_bfloat16 h = __float2bfloat16(v);
    H[idx] = h;
    L[idx] = __float2bfloat16(v - __bfloat162float(h));
}

// ================= spline =================
__device__ __forceinline__ float softplusf(float x) {
    return (x > 0.f) ? (x + log1pf(expf(-x))) : log1pf(expf(x));
}

__global__ void __launch_bounds__(256) spline_kernel(
    const float* __restrict__ y, int ldy,
    const float* __restrict__ cond,
    float* __restrict__ out_y, int ldo,
    float* __restrict__ logdet, int add,
    __nv_bfloat16* __restrict__ upH, __nv_bfloat16* __restrict__ upL)
{
    const int gid = blockIdx.x * 256 + threadIdx.x;
    const int s   = gid >> 5;
    const int dim = gid & 31;
    if (s >= NS) return;

    const float* p = cond + (size_t)s * NOUTP + dim * 23;
    const float x = y[(size_t)s * ldy + dim];

    float rw[KB], rh[KB];
#pragma unroll
    for (int i = 0; i < KB; i++) rw[i] = p[i];
#pragma unroll
    for (int i = 0; i < KB; i++) rh[i] = p[KB + i];

    float cw[KB + 1], wid[KB];
    {
        float m = rw[0];
#pragma unroll
        for (int i = 1; i < KB; i++) m = fmaxf(m, rw[i]);
        float s1 = 0.f, e[KB];
#pragma unroll
        for (int i = 0; i < KB; i++) { e[i] = expf(rw[i] - m); s1 += e[i]; }
        float inv1 = 1.f / s1, Wv[KB];
#pragma unroll
        for (int i = 0; i < KB; i++) Wv[i] = 2.f * TB * e[i] * inv1;
        float m2 = Wv[0];
#pragma unroll
        for (int i = 1; i < KB; i++) m2 = fmaxf(m2, Wv[i]);
        float s2 = 0.f;
#pragma unroll
        for (int i = 0; i < KB; i++) { e[i] = expf(Wv[i] - m2); s2 += e[i]; }
        float inv2 = 1.f / s2;
        float run = 0.f;
        cw[0] = -TB;
#pragma unroll
        for (int i = 0; i < KB; i++) {
            float w = 0.001f + (1.f - 0.001f * KB) * e[i] * inv2;
            run += w;
            cw[i + 1] = 2.f * TB * run - TB;
        }
        cw[KB] = TB;
#pragma unroll
        for (int i = 0; i < KB; i++) wid[i] = cw[i + 1] - cw[i];
    }

    float ch[KB + 1], hei[KB];
    {
        float m = rh[0];
#pragma unroll
        for (int i = 1; i < KB; i++) m = fmaxf(m, rh[i]);
        float s1 = 0.f, e[KB];
#pragma unroll
        for (int i = 0; i < KB; i++) { e[i] = expf(rh[i] - m); s1 += e[i]; }
        float inv1 = 1.f / s1, Hv[KB];
#pragma unroll
        for (int i = 0; i < KB; i++) Hv[i] = 2.f * TB * e[i] * inv1;
        float m2 = Hv[0];
#pragma unroll
        for (int i = 1; i < KB; i++) m2 = fmaxf(m2, Hv[i]);
        float s2 = 0.f;
#pragma unroll
        for (int i = 0; i < KB; i++) { e[i] = expf(Hv[i] - m2); s2 += e[i]; }
        float inv2 = 1.f / s2;
        float run = 0.f;
        ch[0] = -TB;
#pragma unroll
        for (int i = 0; i < KB; i++) {
            float h = 0.001f + (1.f - 0.001f * KB) * e[i] * inv2;
            run += h;
            ch[i + 1] = 2.f * TB * run - TB;
        }
        ch[KB] = TB;
#pragma unroll
        for (int i = 0; i < KB; i++) hei[i] = ch[i + 1] - ch[i];
    }

    float der[KB + 1];
    {
        const float CONST = 0.5397432446f;
        der[0] = 0.001f + softplusf(CONST);
        der[KB] = der[0];
#pragma unroll
        for (int i = 0; i < KB - 1; i++)
            der[i + 1] = 0.001f + softplusf(softplusf(p[2 * KB + i]));
    }

    const bool inside = (x >= -TB) && (x <= TB);
    const float xc = fminf(fmaxf(x, -TB), TB);
    int cnt = 0;
#pragma unroll
    for (int j = 0; j <= KB; j++) {
        float ce = cw[j] + ((j == KB) ? 1e-6f : 0.f);
        cnt += (xc >= ce) ? 1 : 0;
    }
    int idx = min(max(cnt - 1, 0), KB - 1);

    float in_cw = 0.f, in_w = 1.f, in_ch = 0.f, in_h = 1.f, in_der = 1.f, in_der1 = 1.f;
#pragma unroll
    for (int j = 0; j < KB; j++) {
        if (j == idx) {
            in_cw = cw[j]; in_w = wid[j]; in_ch = ch[j]; in_h = hei[j];
            in_der = der[j]; in_der1 = der[j + 1];
        }
    }
    const float in_d = in_h / in_w;
    const float theta = (xc - in_cw) / in_w;
    const float t1mt  = theta * (1.f - theta);
    const float num   = in_h * (in_d * theta * theta + in_der * t1mt);
    const float den   = in_d + (in_der + in_der1 - 2.f * in_d) * t1mt;
    const float outv  = in_ch + num / den;
    const float omt   = 1.f - theta;
    const float dnum  = in_d * in_d * (in_der1 * theta * theta + 2.f * in_d * t1mt + in_der * omt * omt);
    float lad = logf(dnum) - 2.f * logf(den);

    const float fv = inside ? outv : x;
    out_y[(size_t)s * ldo + dim] = fv;
    lad = inside ? lad : 0.f;

    if (upH) {
        __nv_bfloat16 h = __float2bfloat16(fv);
        float rem = fv - __bfloat162float(h);
        upH[(size_t)s * 64 + dim] = h;
        upL[(size_t)s * 64 + dim] = __float2bfloat16(rem);
        upH[(size_t)s * 64 + 32 + dim] = __float2bfloat16(0.f);
        upL[(size_t)s * 64 + 32 + dim] = __float2bfloat16(0.f);
    }

#pragma unroll
    for (int off = 16; off > 0; off >>= 1)
        lad += __shfl_down_sync(0xffffffffu, lad, off);
    if (dim == 0) {
        if (add) logdet[s] += lad;
        else     logdet[s]  = lad;
    }
}

// ================= launch =================
extern "C" void kernel_launch(void* const* d_in, const int* in_sizes, int n_in,
                              void* d_out, int out_size)
{
    const float* x = (const float*)d_in[0];
    const float* w[2][4] = {{(const float*)d_in[1], (const float*)d_in[3], (const float*)d_in[5], (const float*)d_in[7]},
                            {(const float*)d_in[9], (const float*)d_in[11], (const float*)d_in[13], (const float*)d_in[15]}};
    const float* bb[2][4] = {{(const float*)d_in[2], (const float*)d_in[4], (const float*)d_in[6], (const float*)d_in[8]},
                             {(const float*)d_in[10], (const float*)d_in[12], (const float*)d_in[14], (const float*)d_in[16]}};

    float* out    = (float*)d_out;
    float* logdet = out + (size_t)NS * 64;

    __nv_bfloat16 *xH, *xL, *aH0, *aL0, *aH1, *aL1;
    __nv_bfloat16 *w1H, *w1L, *w2H, *w2L, *w3H, *w3L, *w4H, *w4L;
    float *bufC, *b4p;
    cudaGetSymbolAddress((void**)&xH, g_xH);   cudaGetSymbolAddress((void**)&xL, g_xL);
    cudaGetSymbolAddress((void**)&aH0, g_aH0); cudaGetSymbolAddress((void**)&aL0, g_aL0);
    cudaGetSymbolAddress((void**)&aH1, g_aH1); cudaGetSymbolAddress((void**)&aL1, g_aL1);
    cudaGetSymbolAddress((void**)&w1H, g_w1H); cudaGetSymbolAddress((void**)&w1L, g_w1L);
    cudaGetSymbolAddress((void**)&w2H, g_w2H); cudaGetSymbolAddress((void**)&w2L, g_w2L);
    cudaGetSymbolAddress((void**)&w3H, g_w3H); cudaGetSymbolAddress((void**)&w3L, g_w3L);
    cudaGetSymbolAddress((void**)&w4H, g_w4H); cudaGetSymbolAddress((void**)&w4L, g_w4L);
    cudaGetSymbolAddress((void**)&bufC, g_bufC);
    cudaGetSymbolAddress((void**)&b4p, g_b4p);

    cudaFuncSetAttribute(gemm_bf16x2<1,1,1>, cudaFuncAttributeMaxDynamicSharedMemorySize, SMEM_TOTAL);
    cudaFuncSetAttribute(gemm_bf16x2<8,1,1>, cudaFuncAttributeMaxDynamicSharedMemorySize, SMEM_TOTAL);
    cudaFuncSetAttribute(gemm_bf16x2<8,0,0>, cudaFuncAttributeMaxDynamicSharedMemorySize, SMEM_TOTAL);

    for (int c = 0; c < 2; c++) {
        prep_w<<<(512*64 + 255)/256, 256>>>(w[c][0], nullptr, HALF, NHID, 64, 512,
                                            w1H + c*512*64, w1L + c*512*64, nullptr);
        prep_w<<<(512*512 + 255)/256, 256>>>(w[c][1], nullptr, NHID, NHID, 512, 512,
                                             w2H + c*512*512, w2L + c*512*512, nullptr);
        prep_w<<<(512*512 + 255)/256, 256>>>(w[c][2], nullptr, NHID, NHID, 512, 512,
                                             w3H + c*512*512, w3L + c*512*512, nullptr);
        prep_w<<<(768*512 + 255)/256, 256>>>(w[c][3], bb[c][3], NHID, NOUT, 512, NOUTP,
                                             w4H + c*768*512, w4L + c*768*512, b4p + c*NOUTP);
    }
    split_x<<<(NS*64)/256, 256>>>(x, xH, xL);

    const dim3 blk(NTHR);
    const dim3 g512(NHID / BN, NS / BM);   // (4, 512)
    const dim3 g768(NOUTP / BN, NS / BM);  // (6, 512)
    const int splineBlocks = (NS * 32) / 256;

    for (int c = 0; c < 2; c++) {
        gemm_bf16x2<1,1,1><<<g512, blk, SMEM_TOTAL>>>(xH, xL, 64,
            w1H + c*512*64, w1L + c*512*64, bb[c][0], aH0, aL0, nullptr, NHID);
        gemm_bf16x2<8,1,1><<<g512, blk, SMEM_TOTAL>>>(aH0, aL0, NHID,
            w2H + c*512*512, w2L + c*512*512, bb[c][1], aH1, aL1, nullptr, NHID);
        gemm_bf16x2<8,1,1><<<g512, blk, SMEM_TOTAL>>>(aH1, aL1, NHID,
            w3H + c*512*512, w3L + c*512*512, bb[c][2], aH0, aL0, nullptr, NHID);
        gemm_bf16x2<8,0,0><<<g768, blk, SMEM_TOTAL>>>(aH0, aL0, NHID,
            w4H + c*768*512, w4L + c*768*512, b4p + c*NOUTP, nullptr, nullptr, bufC, NOUTP);
        if (c == 0)
            spline_kernel<<<splineBlocks, blk>>>(x + HALF, 64, bufC, out + HALF, 64, logdet, 0, xH, xL);
        else
            spline_kernel<<<splineBlocks, blk>>>(x, 64, bufC, out, 64, logdet, 1, nullptr, nullptr);
    }
}